// round 1
// baseline (speedup 1.0000x reference)
#include <cuda_runtime.h>
#include <math.h>

#define B_   8
#define C_   512
#define N_   2048
#define GROUPS_ 32
#define CPG  (C_/GROUPS_)     // 16
#define EPSF 1e-6f

// ---------------- scratch (static device globals; no allocation) ----------------
__device__ float g_h [B_*C_*N_];   // groupnorm output            32 MB
__device__ float g_q [B_*C_*N_];   // q                           32 MB
__device__ float g_k [B_*C_*N_];   // k                           32 MB
__device__ float g_v [B_*C_*N_];   // v                           32 MB
__device__ float g_p [(size_t)B_*N_*N_]; // attn logits/probs    128 MB
__device__ float g_h2[B_*C_*N_];   // attention output            32 MB

// ---------------- GroupNorm ----------------
// one block per (b, g): reduce over 16 channels x 2048 = 32768 elems
__global__ __launch_bounds__(256) void groupnorm_kernel(const float* __restrict__ x,
                                                        const float* __restrict__ scale,
                                                        const float* __restrict__ bias) {
    int bg = blockIdx.x;
    int b = bg / GROUPS_, g = bg % GROUPS_;
    const float* xp = x   + ((size_t)b*C_ + (size_t)g*CPG) * N_;
    float*       hp = g_h + ((size_t)b*C_ + (size_t)g*CPG) * N_;
    int tid = threadIdx.x;
    const int total = CPG * N_;  // 32768

    float s = 0.f, ss = 0.f;
    for (int i = tid; i < total; i += 256) {
        float v = xp[i];
        s += v; ss += v * v;
    }
    __shared__ float rs[256], rq[256];
    rs[tid] = s; rq[tid] = ss;
    __syncthreads();
    for (int off = 128; off > 0; off >>= 1) {
        if (tid < off) { rs[tid] += rs[tid+off]; rq[tid] += rq[tid+off]; }
        __syncthreads();
    }
    float mean = rs[0] / (float)total;
    float var  = rq[0] / (float)total - mean * mean;
    float rinv = rsqrtf(var + EPSF);

    for (int i = tid; i < total; i += 256) {
        int c = g*CPG + (i >> 11);                 // i / N_ (N_=2048)
        hp[i] = (xp[i] - mean) * rinv * scale[c] + bias[c];
    }
}

// ---------------- fused QKV GEMM ----------------
// out[b][o][n] = sum_c W[o][c] * h[b][c][n] + bias[o]
// grid: (N_/128=16, C_/128=4, B_*3=24), 256 threads, 128x128x8 tile, 8x8/thread
__global__ __launch_bounds__(256) void qkv_kernel(const float* __restrict__ wq, const float* __restrict__ bq,
                                                  const float* __restrict__ wk, const float* __restrict__ bk,
                                                  const float* __restrict__ wv, const float* __restrict__ bv) {
    int z = blockIdx.z;
    int b = z / 3, which = z % 3;
    const float* W    = (which == 0) ? wq : (which == 1) ? wk : wv;
    const float* bias = (which == 0) ? bq : (which == 1) ? bk : bv;
    float* out = ((which == 0) ? g_q : (which == 1) ? g_k : g_v) + (size_t)b*C_*N_;
    const float* H = g_h + (size_t)b*C_*N_;

    int m0 = blockIdx.y * 128;
    int n0 = blockIdx.x * 128;
    int tid = threadIdx.x;
    int tr = tid >> 4, tc = tid & 15;

    __shared__ float As[8][132];
    __shared__ float Bs[8][132];
    float acc[8][8] = {};

    for (int k0 = 0; k0 < C_; k0 += 8) {
        #pragma unroll
        for (int i = 0; i < 4; i++) {                 // A: W tile (transpose to [k][m])
            int idx = tid*4 + i;
            int m = idx >> 3, k = idx & 7;
            As[k][m] = W[(size_t)(m0+m)*C_ + k0 + k];
        }
        #pragma unroll
        for (int i = 0; i < 4; i++) {                 // B: H tile, n contiguous
            int idx = tid + i*256;
            int k = idx >> 7, n = idx & 127;
            Bs[k][n] = H[(size_t)(k0+k)*N_ + n0 + n];
        }
        __syncthreads();
        #pragma unroll
        for (int kk = 0; kk < 8; kk++) {
            float a[8], bb[8];
            #pragma unroll
            for (int i = 0; i < 8; i++) a[i]  = As[kk][tr*8 + i];
            #pragma unroll
            for (int j = 0; j < 8; j++) bb[j] = Bs[kk][tc*8 + j];
            #pragma unroll
            for (int i = 0; i < 8; i++)
                #pragma unroll
                for (int j = 0; j < 8; j++)
                    acc[i][j] += a[i] * bb[j];
        }
        __syncthreads();
    }
    #pragma unroll
    for (int i = 0; i < 8; i++) {
        int o = m0 + tr*8 + i;
        float bo = bias[o];
        #pragma unroll
        for (int j = 0; j < 8; j++)
            out[(size_t)o*N_ + n0 + tc*8 + j] = acc[i][j] + bo;
    }
}

// ---------------- QK^T GEMM ----------------
// p[b][i][j] = scale * sum_c q[b][c][i] * k[b][c][j]
// grid: (16, 16, 8)
__global__ __launch_bounds__(256) void qk_kernel() {
    int b = blockIdx.z;
    const float* Q  = g_q + (size_t)b*C_*N_;
    const float* Kk = g_k + (size_t)b*C_*N_;
    float* P = g_p + (size_t)b*N_*N_;

    int i0 = blockIdx.y * 128;
    int j0 = blockIdx.x * 128;
    int tid = threadIdx.x;
    int tr = tid >> 4, tc = tid & 15;

    __shared__ float As[8][132];
    __shared__ float Bs[8][132];
    float acc[8][8] = {};

    for (int k0 = 0; k0 < C_; k0 += 8) {
        #pragma unroll
        for (int t = 0; t < 4; t++) {
            int idx = tid + t*256;
            int k = idx >> 7, m = idx & 127;
            As[k][m] = Q [(size_t)(k0+k)*N_ + i0 + m];
            Bs[k][m] = Kk[(size_t)(k0+k)*N_ + j0 + m];
        }
        __syncthreads();
        #pragma unroll
        for (int kk = 0; kk < 8; kk++) {
            float a[8], bb[8];
            #pragma unroll
            for (int i = 0; i < 8; i++) a[i]  = As[kk][tr*8 + i];
            #pragma unroll
            for (int j = 0; j < 8; j++) bb[j] = Bs[kk][tc*8 + j];
            #pragma unroll
            for (int i = 0; i < 8; i++)
                #pragma unroll
                for (int j = 0; j < 8; j++)
                    acc[i][j] += a[i] * bb[j];
        }
        __syncthreads();
    }
    const float scale = 0.044194173824159216f;   // 512^-0.5
    #pragma unroll
    for (int i = 0; i < 8; i++)
        #pragma unroll
        for (int j = 0; j < 8; j++)
            P[(size_t)(i0 + tr*8 + i)*N_ + j0 + tc*8 + j] = acc[i][j] * scale;
}

// ---------------- row softmax over keys ----------------
// one block per row (16384 rows of length 2048)
__global__ __launch_bounds__(256) void softmax_kernel() {
    size_t row = blockIdx.x;
    float* p = g_p + row * N_;
    int tid = threadIdx.x;

    float v[8];
    float mx = -1e30f;
    #pragma unroll
    for (int j = 0; j < 8; j++) { v[j] = p[tid + j*256]; mx = fmaxf(mx, v[j]); }

    __shared__ float red[256];
    red[tid] = mx; __syncthreads();
    for (int off = 128; off > 0; off >>= 1) {
        if (tid < off) red[tid] = fmaxf(red[tid], red[tid+off]);
        __syncthreads();
    }
    mx = red[0]; __syncthreads();

    float s = 0.f;
    #pragma unroll
    for (int j = 0; j < 8; j++) { v[j] = expf(v[j] - mx); s += v[j]; }
    red[tid] = s; __syncthreads();
    for (int off = 128; off > 0; off >>= 1) {
        if (tid < off) red[tid] += red[tid+off];
        __syncthreads();
    }
    float rinv = 1.f / red[0];
    #pragma unroll
    for (int j = 0; j < 8; j++) p[tid + j*256] = v[j] * rinv;
}

// ---------------- PV GEMM ----------------
// h2[b][c][i] = sum_j v[b][c][j] * P[b][i][j]   (K = 2048)
// grid: (16, 4, 8)
__global__ __launch_bounds__(256) void pv_kernel() {
    int b = blockIdx.z;
    const float* V = g_v + (size_t)b*C_*N_;
    const float* P = g_p + (size_t)b*N_*N_;
    float* H2 = g_h2 + (size_t)b*C_*N_;

    int c0 = blockIdx.y * 128;
    int i0 = blockIdx.x * 128;
    int tid = threadIdx.x;
    int tr = tid >> 4, tc = tid & 15;

    __shared__ float As[8][132];
    __shared__ float Bs[8][132];
    float acc[8][8] = {};

    for (int k0 = 0; k0 < N_; k0 += 8) {
        #pragma unroll
        for (int t = 0; t < 4; t++) {                // A: V tile (c-rows, j contiguous) -> [k][c]
            int idx = tid*4 + t;
            int cl = idx >> 3, k = idx & 7;
            As[k][cl] = V[(size_t)(c0+cl)*N_ + k0 + k];
        }
        #pragma unroll
        for (int t = 0; t < 4; t++) {                // B: P tile (i-rows, j contiguous) -> [k][i]
            int idx = tid*4 + t;
            int il = idx >> 3, k = idx & 7;
            Bs[k][il] = P[(size_t)(i0+il)*N_ + k0 + k];
        }
        __syncthreads();
        #pragma unroll
        for (int kk = 0; kk < 8; kk++) {
            float a[8], bb[8];
            #pragma unroll
            for (int i = 0; i < 8; i++) a[i]  = As[kk][tr*8 + i];
            #pragma unroll
            for (int j = 0; j < 8; j++) bb[j] = Bs[kk][tc*8 + j];
            #pragma unroll
            for (int i = 0; i < 8; i++)
                #pragma unroll
                for (int j = 0; j < 8; j++)
                    acc[i][j] += a[i] * bb[j];
        }
        __syncthreads();
    }
    #pragma unroll
    for (int i = 0; i < 8; i++)
        #pragma unroll
        for (int j = 0; j < 8; j++)
            H2[(size_t)(c0 + tr*8 + i)*N_ + i0 + tc*8 + j] = acc[i][j];
}

// ---------------- proj GEMM + residual ----------------
// out[b][o][n] = x[b][o][n] + bp[o] + sum_c wp[o][c] * h2[b][c][n]
// grid: (16, 4, 8)
__global__ __launch_bounds__(256) void proj_kernel(const float* __restrict__ x,
                                                   const float* __restrict__ wp,
                                                   const float* __restrict__ bp,
                                                   float* __restrict__ out) {
    int b = blockIdx.z;
    const float* H2 = g_h2 + (size_t)b*C_*N_;

    int m0 = blockIdx.y * 128;
    int n0 = blockIdx.x * 128;
    int tid = threadIdx.x;
    int tr = tid >> 4, tc = tid & 15;

    __shared__ float As[8][132];
    __shared__ float Bs[8][132];
    float acc[8][8] = {};

    for (int k0 = 0; k0 < C_; k0 += 8) {
        #pragma unroll
        for (int i = 0; i < 4; i++) {
            int idx = tid*4 + i;
            int m = idx >> 3, k = idx & 7;
            As[k][m] = wp[(size_t)(m0+m)*C_ + k0 + k];
        }
        #pragma unroll
        for (int i = 0; i < 4; i++) {
            int idx = tid + i*256;
            int k = idx >> 7, n = idx & 127;
            Bs[k][n] = H2[(size_t)(k0+k)*N_ + n0 + n];
        }
        __syncthreads();
        #pragma unroll
        for (int kk = 0; kk < 8; kk++) {
            float a[8], bb[8];
            #pragma unroll
            for (int i = 0; i < 8; i++) a[i]  = As[kk][tr*8 + i];
            #pragma unroll
            for (int j = 0; j < 8; j++) bb[j] = Bs[kk][tc*8 + j];
            #pragma unroll
            for (int i = 0; i < 8; i++)
                #pragma unroll
                for (int j = 0; j < 8; j++)
                    acc[i][j] += a[i] * bb[j];
        }
        __syncthreads();
    }
    #pragma unroll
    for (int i = 0; i < 8; i++) {
        int o = m0 + tr*8 + i;
        float bo = bp[o];
        #pragma unroll
        for (int j = 0; j < 8; j++) {
            size_t idx = ((size_t)b*C_ + o)*N_ + n0 + tc*8 + j;
            out[idx] = x[idx] + acc[i][j] + bo;
        }
    }
}

// ---------------- launch ----------------
extern "C" void kernel_launch(void* const* d_in, const int* in_sizes, int n_in,
                              void* d_out, int out_size) {
    const float* x  = (const float*)d_in[0];
    const float* gs = (const float*)d_in[1];
    const float* gb = (const float*)d_in[2];
    const float* wq = (const float*)d_in[3];
    const float* bq = (const float*)d_in[4];
    const float* wk = (const float*)d_in[5];
    const float* bk = (const float*)d_in[6];
    const float* wv = (const float*)d_in[7];
    const float* bv = (const float*)d_in[8];
    const float* wp = (const float*)d_in[9];
    const float* bp = (const float*)d_in[10];
    float* out = (float*)d_out;

    groupnorm_kernel<<<B_*GROUPS_, 256>>>(x, gs, gb);

    dim3 gqkv(N_/128, C_/128, B_*3);
    qkv_kernel<<<gqkv, 256>>>(wq, bq, wk, bk, wv, bv);

    dim3 gqk(N_/128, N_/128, B_);
    qk_kernel<<<gqk, 256>>>();

    softmax_kernel<<<B_*N_, 256>>>();

    dim3 gpv(N_/128, C_/128, B_);
    pv_kernel<<<gpv, 256>>>();

    dim3 gproj(N_/128, C_/128, B_);
    proj_kernel<<<gproj, 256>>>(x, wp, bp, out);
}

// round 5
// speedup vs baseline: 3.7834x; 3.7834x over previous
#include <cuda_runtime.h>
#include <cstdint>
#include <math.h>

#define B_   8
#define C_   512
#define N_   2048
#define GROUPS_ 32
#define CPG  16
#define EPSF 1e-6f

#define NC_ ((size_t)N_ * C_)      // 1048576
#define NN_ ((size_t)N_ * N_)      // 4194304

// ---------------- scratch ----------------
__device__ float g_hT [B_ * N_ * C_];          // groupnorm out, [b][n][c]
__device__ float g_qT [B_ * N_ * C_];          // [b][n][c]
__device__ float g_kT [B_ * N_ * C_];          // [b][n][c]
__device__ float g_v  [B_ * C_ * N_];          // [b][c][n]
__device__ float g_p  [(size_t)B_ * N_ * N_];  // [b][i][j]
__device__ float g_h2T[B_ * N_ * C_];          // [b][i][c]

// ---------------- helpers ----------------
__device__ __forceinline__ uint32_t smem_u32(const void* p) {
    uint32_t a;
    asm("{ .reg .u64 t; cvta.to.shared.u64 t, %1; cvt.u32.u64 %0, t; }" : "=r"(a) : "l"(p));
    return a;
}
__device__ __forceinline__ void cp_async16(uint32_t dst, const void* src) {
    asm volatile("cp.async.cg.shared.global [%0], [%1], 16;" :: "r"(dst), "l"(src));
}
#define CP_COMMIT() asm volatile("cp.async.commit_group;" ::: "memory")
#define CP_WAIT1()  asm volatile("cp.async.wait_group 1;" ::: "memory")

__device__ __forceinline__ uint32_t to_tf32(float f) {
    uint32_t u;
    asm("cvt.rna.tf32.f32 %0, %1;" : "=r"(u) : "f"(f));
    return u;
}
__device__ __forceinline__ void mma_tf32(float* c, const uint32_t* a, const uint32_t* b) {
    asm volatile("mma.sync.aligned.m16n8k8.row.col.f32.tf32.tf32.f32 "
                 "{%0,%1,%2,%3}, {%4,%5,%6,%7}, {%8,%9}, {%0,%1,%2,%3};"
                 : "+f"(c[0]), "+f"(c[1]), "+f"(c[2]), "+f"(c[3])
                 : "r"(a[0]), "r"(a[1]), "r"(a[2]), "r"(a[3]), "r"(b[0]), "r"(b[1]));
}

// ---------------- GroupNorm (writes transposed hT[b][n][c] via smem tile) ----------------
__global__ __launch_bounds__(256) void groupnorm_kernel(const float* __restrict__ x,
                                                        const float* __restrict__ scale,
                                                        const float* __restrict__ bias) {
    int bg = blockIdx.x;
    int b = bg / GROUPS_, g = bg % GROUPS_;
    const float* xp  = x + ((size_t)b * C_ + (size_t)g * CPG) * N_;
    float*       hpT = g_hT + (size_t)b * NC_;
    int tid = threadIdx.x;
    const int total = CPG * N_;  // 32768

    float s = 0.f, ss = 0.f;
    for (int i = tid; i < total; i += 256) {
        float v = xp[i];
        s += v; ss += v * v;
    }
    __shared__ float rs[256], rq[256];
    rs[tid] = s; rq[tid] = ss;
    __syncthreads();
    for (int off = 128; off > 0; off >>= 1) {
        if (tid < off) { rs[tid] += rs[tid + off]; rq[tid] += rq[tid + off]; }
        __syncthreads();
    }
    float mean = rs[0] / (float)total;
    float var  = rq[0] / (float)total - mean * mean;
    float rinv = rsqrtf(var + EPSF);

    __shared__ float tile[128][17];
    for (int n0 = 0; n0 < N_; n0 += 128) {
        __syncthreads();
        int nl = tid & 127;
        int ch = tid >> 7;               // 0 or 1
        #pragma unroll
        for (int cp = 0; cp < 8; cp++) {
            int c = cp * 2 + ch;         // 0..15
            int cabs = g * CPG + c;
            tile[nl][c] = (xp[(size_t)c * N_ + n0 + nl] - mean) * rinv * scale[cabs] + bias[cabs];
        }
        __syncthreads();
        int row = tid >> 1;              // 0..127
        int half = (tid & 1) * 8;        // 0 or 8
        float* dst = hpT + (size_t)(n0 + row) * C_ + g * CPG + half;
        float4 o0, o1;
        o0.x = tile[row][half + 0]; o0.y = tile[row][half + 1];
        o0.z = tile[row][half + 2]; o0.w = tile[row][half + 3];
        o1.x = tile[row][half + 4]; o1.y = tile[row][half + 5];
        o1.z = tile[row][half + 6]; o1.w = tile[row][half + 7];
        *(float4*)(dst + 0) = o0;
        *(float4*)(dst + 4) = o1;
    }
}

// ---------------- tf32 mma.sync GEMM ----------------
// D[m][n] = sum_k A[m][k] * B[n][k], both K-major. Tile 128x128x16, cp.async 2-stage.
#define MODE_COLB  0
#define MODE_ROWB  1
#define MODE_SCALE 2
#define MODE_NONE  3
#define MODE_OUT   4

#define BK   16
#define PAD  20   // row pitch in floats; (20m+k)%32 distinct over 8m x 4k footprint

template <int MODE>
__global__ __launch_bounds__(256)
void gemm_kernel(const float* __restrict__ A, const float* __restrict__ Bm,
                 float* __restrict__ D,
                 const float* __restrict__ bias, const float* __restrict__ resid,
                 int lda, int ldb, int ldd, int K,
                 size_t a_bs, size_t b_bs, size_t d_bs, size_t r_bs) {
    __shared__ float sA[2][128 * PAD];   // 10 KB each
    __shared__ float sB[2][128 * PAD];

    int tid = threadIdx.x, lane = tid & 31, wid = tid >> 5;
    int warp_m = wid & 3;                // 4 warps over M
    int warp_n = wid >> 2;               // 2 warps over N

    int b  = blockIdx.z;
    int m0 = blockIdx.y * 128, n0 = blockIdx.x * 128;
    const float* Ab = A  + (size_t)b * a_bs;
    const float* Bb = Bm + (size_t)b * b_bs;
    float*       Db = D  + (size_t)b * d_bs;

    uint32_t saddr = smem_u32(sA);
    uint32_t baddr = smem_u32(sB);

    // global-load mapping: 512 float4 per operand per chunk; thread does idx=tid, tid+256
    int lr0 = tid >> 2, lc0 = tid & 3;          // row 0..63, col 0..3
    int lr1 = lr0 + 64;

    auto load_stage = [&](int stage, int k0) {
        uint32_t sa = saddr + (uint32_t)stage * 128 * PAD * 4;
        uint32_t sb = baddr + (uint32_t)stage * 128 * PAD * 4;
        cp_async16(sa + (uint32_t)(lr0 * PAD + lc0 * 4) * 4, Ab + (size_t)(m0 + lr0) * lda + k0 + lc0 * 4);
        cp_async16(sa + (uint32_t)(lr1 * PAD + lc0 * 4) * 4, Ab + (size_t)(m0 + lr1) * lda + k0 + lc0 * 4);
        cp_async16(sb + (uint32_t)(lr0 * PAD + lc0 * 4) * 4, Bb + (size_t)(n0 + lr0) * ldb + k0 + lc0 * 4);
        cp_async16(sb + (uint32_t)(lr1 * PAD + lc0 * 4) * 4, Bb + (size_t)(n0 + lr1) * ldb + k0 + lc0 * 4);
    };

    float acc[2][8][4];
    #pragma unroll
    for (int i = 0; i < 2; i++)
        #pragma unroll
        for (int j = 0; j < 8; j++)
            #pragma unroll
            for (int t = 0; t < 4; t++) acc[i][j][t] = 0.f;

    const int nck = K / BK;
    load_stage(0, 0);
    CP_COMMIT();

    for (int ck = 0; ck < nck; ck++) {
        if (ck + 1 < nck) load_stage((ck + 1) & 1, (ck + 1) * BK);
        CP_COMMIT();
        CP_WAIT1();
        __syncthreads();

        const float* sa = sA[ck & 1];
        const float* sb = sB[ck & 1];
        int arow = warp_m * 32 + (lane >> 2);
        int brow = warp_n * 64 + (lane >> 2);
        int kq   = lane & 3;

        #pragma unroll
        for (int kk = 0; kk < 2; kk++) {
            int kbase = kk * 8 + kq;
            uint32_t af[2][4];
            #pragma unroll
            for (int mt = 0; mt < 2; mt++) {
                const float* ap = sa + (arow + mt * 16) * PAD + kbase;
                af[mt][0] = to_tf32(ap[0]);
                af[mt][1] = to_tf32(ap[8 * PAD]);
                af[mt][2] = to_tf32(ap[4]);
                af[mt][3] = to_tf32(ap[8 * PAD + 4]);
            }
            uint32_t bf[8][2];
            #pragma unroll
            for (int nt = 0; nt < 8; nt++) {
                const float* bp = sb + (brow + nt * 8) * PAD + kbase;
                bf[nt][0] = to_tf32(bp[0]);
                bf[nt][1] = to_tf32(bp[4]);
            }
            #pragma unroll
            for (int mt = 0; mt < 2; mt++)
                #pragma unroll
                for (int nt = 0; nt < 8; nt++)
                    mma_tf32(acc[mt][nt], af[mt], bf[nt]);
        }
        __syncthreads();
    }

    // epilogue: c0,c1 -> (row, col), (row, col+1); c2,c3 -> (row+8, col..)
    int rbase = m0 + warp_m * 32 + (lane >> 2);
    int cbase = n0 + warp_n * 64 + (lane & 3) * 2;
    #pragma unroll
    for (int mt = 0; mt < 2; mt++) {
        int r0 = rbase + mt * 16;
        int r1 = r0 + 8;
        float rb0 = 0.f, rb1 = 0.f;
        if (MODE == MODE_ROWB || MODE == MODE_OUT) { rb0 = bias[r0]; rb1 = bias[r1]; }
        #pragma unroll
        for (int nt = 0; nt < 8; nt++) {
            int cc = cbase + nt * 8;
            float e0 = acc[mt][nt][0], e1 = acc[mt][nt][1];
            float e2 = acc[mt][nt][2], e3 = acc[mt][nt][3];
            if (MODE == MODE_COLB) {
                float b0 = bias[cc], b1 = bias[cc + 1];
                e0 += b0; e1 += b1; e2 += b0; e3 += b1;
            } else if (MODE == MODE_SCALE) {
                const float scl = 0.044194173824159216f;
                e0 *= scl; e1 *= scl; e2 *= scl; e3 *= scl;
            } else if (MODE == MODE_ROWB) {
                e0 += rb0; e1 += rb0; e2 += rb1; e3 += rb1;
            } else if (MODE == MODE_OUT) {
                const float* rp0 = resid + (size_t)b * r_bs + (size_t)r0 * ldd + cc;
                const float* rp1 = resid + (size_t)b * r_bs + (size_t)r1 * ldd + cc;
                e0 += rb0 + rp0[0]; e1 += rb0 + rp0[1];
                e2 += rb1 + rp1[0]; e3 += rb1 + rp1[1];
            }
            float2 o0; o0.x = e0; o0.y = e1;
            float2 o1; o1.x = e2; o1.y = e3;
            *(float2*)(Db + (size_t)r0 * ldd + cc) = o0;
            *(float2*)(Db + (size_t)r1 * ldd + cc) = o1;
        }
    }
}

// ---------------- row softmax ----------------
__global__ __launch_bounds__(256) void softmax_kernel() {
    size_t row = blockIdx.x;
    float* p = g_p + row * N_;
    int tid = threadIdx.x;

    float v[8];
    float mx = -1e30f;
    #pragma unroll
    for (int j = 0; j < 8; j++) { v[j] = p[tid + j * 256]; mx = fmaxf(mx, v[j]); }

    __shared__ float red[256];
    red[tid] = mx; __syncthreads();
    for (int off = 128; off > 0; off >>= 1) {
        if (tid < off) red[tid] = fmaxf(red[tid], red[tid + off]);
        __syncthreads();
    }
    mx = red[0]; __syncthreads();

    float s = 0.f;
    #pragma unroll
    for (int j = 0; j < 8; j++) { v[j] = expf(v[j] - mx); s += v[j]; }
    red[tid] = s; __syncthreads();
    for (int off = 128; off > 0; off >>= 1) {
        if (tid < off) red[tid] += red[tid + off];
        __syncthreads();
    }
    float rinv = 1.f / red[0];
    #pragma unroll
    for (int j = 0; j < 8; j++) p[tid + j * 256] = v[j] * rinv;
}

// ---------------- launch ----------------
extern "C" void kernel_launch(void* const* d_in, const int* in_sizes, int n_in,
                              void* d_out, int out_size) {
    const float* x  = (const float*)d_in[0];
    const float* gs = (const float*)d_in[1];
    const float* gb = (const float*)d_in[2];
    const float* wq = (const float*)d_in[3];
    const float* bq = (const float*)d_in[4];
    const float* wk = (const float*)d_in[5];
    const float* bk = (const float*)d_in[6];
    const float* wv = (const float*)d_in[7];
    const float* bv = (const float*)d_in[8];
    const float* wp = (const float*)d_in[9];
    const float* bp = (const float*)d_in[10];
    float* out = (float*)d_out;

    float* hT  = nullptr; cudaGetSymbolAddress((void**)&hT,  g_hT);
    float* qT  = nullptr; cudaGetSymbolAddress((void**)&qT,  g_qT);
    float* kT  = nullptr; cudaGetSymbolAddress((void**)&kT,  g_kT);
    float* v   = nullptr; cudaGetSymbolAddress((void**)&v,   g_v);
    float* p   = nullptr; cudaGetSymbolAddress((void**)&p,   g_p);
    float* h2T = nullptr; cudaGetSymbolAddress((void**)&h2T, g_h2T);

    groupnorm_kernel<<<B_ * GROUPS_, 256>>>(x, gs, gb);

    // qT[n][o] = sum_c hT[n][c] wq[o][c] + bq[o]      M=2048 N=512 K=512
    gemm_kernel<MODE_COLB><<<dim3(4, 16, B_), 256>>>(
        hT, wq, qT, bq, nullptr, C_, C_, C_, C_, NC_, 0, NC_, 0);
    // kT
    gemm_kernel<MODE_COLB><<<dim3(4, 16, B_), 256>>>(
        hT, wk, kT, bk, nullptr, C_, C_, C_, C_, NC_, 0, NC_, 0);
    // v[o][n] = sum_c wv[o][c] hT[n][c] + bv[o]       M=512 N=2048 K=512
    gemm_kernel<MODE_ROWB><<<dim3(16, 4, B_), 256>>>(
        wv, hT, v, bv, nullptr, C_, C_, N_, C_, 0, NC_, NC_, 0);
    // P[i][j] = scale * sum_c qT[i][c] kT[j][c]       M=2048 N=2048 K=512
    gemm_kernel<MODE_SCALE><<<dim3(16, 16, B_), 256>>>(
        qT, kT, p, nullptr, nullptr, C_, C_, N_, C_, NC_, NC_, NN_, 0);

    softmax_kernel<<<B_ * N_, 256>>>();

    // h2T[i][c] = sum_j P[i][j] v[c][j]               M=2048 N=512 K=2048
    gemm_kernel<MODE_NONE><<<dim3(4, 16, B_), 256>>>(
        p, v, h2T, nullptr, nullptr, N_, N_, C_, N_, NN_, NC_, NC_, 0);
    // out[o][n] = x + bp[o] + sum_c wp[o][c] h2T[n][c]  M=512 N=2048 K=512
    gemm_kernel<MODE_OUT><<<dim3(16, 4, B_), 256>>>(
        wp, h2T, out, bp, x, C_, C_, N_, C_, 0, NC_, NC_, NC_);
}